// round 1
// baseline (speedup 1.0000x reference)
#include <cuda_runtime.h>

// Problem constants
#define BB 4
#define TT 2048
#define CC 2048
#define HH 16
#define DD 128
#define QKSCALE 0.08838834764831845f  // 1/sqrt(128)

// Scratch (device globals: allocation-free rule)
__device__ float g_q[(size_t)BB * HH * TT * DD];   // [B,H,T,D], pre-scaled by 1/sqrt(D)
__device__ float g_k[(size_t)BB * HH * TT * DD];   // [B,H,T,D]
__device__ float g_v[(size_t)BB * HH * TT * DD];   // [B,H,T,D]
__device__ float g_ao[(size_t)BB * TT * CC];       // attention output, [B,T,C]

// ---------------------------------------------------------------------------
// Tiled fp32 GEMM: C[M,N] = A[M,K] @ B[K,N] + bias[N]
// MODE 0: A = x, scatter output into g_q/g_k/g_v ([B,H,T,D] layout, q scaled)
// MODE 1: A = g_ao, plain row-major output to Cout
// Tiling: 128x128 block, BK=16, 256 threads, 8x8 per thread.
// ---------------------------------------------------------------------------
template <int MODE>
__global__ __launch_bounds__(256) void gemm_kernel(
    const float* __restrict__ A, const float* __restrict__ Bm,
    const float* __restrict__ bias, float* __restrict__ Cout,
    int M, int N, int K)
{
    __shared__ float As[16][128];   // transposed: As[k][m]
    __shared__ float Bs[16][128];   // Bs[k][n]

    const float* Ap = (MODE == 1) ? g_ao : A;

    const int tid = threadIdx.x;
    const int tx = tid & 15;        // col group
    const int ty = tid >> 4;        // row group
    const int m0 = blockIdx.y * 128;
    const int n0 = blockIdx.x * 128;

    float acc[8][8];
#pragma unroll
    for (int i = 0; i < 8; i++)
#pragma unroll
        for (int j = 0; j < 8; j++) acc[i][j] = 0.f;

    for (int k0 = 0; k0 < K; k0 += 16) {
        // Load A tile 128x16 (transpose into As[k][m])
#pragma unroll
        for (int i = 0; i < 2; i++) {
            int pp = tid + i * 256;            // 0..511
            int row = pp >> 2;                 // 0..127
            int kq = (pp & 3) * 4;             // 0,4,8,12
            float4 av = *(const float4*)(Ap + (size_t)(m0 + row) * K + k0 + kq);
            As[kq + 0][row] = av.x;
            As[kq + 1][row] = av.y;
            As[kq + 2][row] = av.z;
            As[kq + 3][row] = av.w;
        }
        // Load B tile 16x128
#pragma unroll
        for (int i = 0; i < 2; i++) {
            int pp = tid + i * 256;
            int row = pp >> 5;                 // 0..15
            int nn = (pp & 31) * 4;            // 0..124
            *(float4*)&Bs[row][nn] =
                *(const float4*)(Bm + (size_t)(k0 + row) * N + n0 + nn);
        }
        __syncthreads();

#pragma unroll
        for (int k = 0; k < 16; k++) {
            float a[8], b[8];
            *(float4*)&a[0] = *(float4*)&As[k][ty * 4];
            *(float4*)&a[4] = *(float4*)&As[k][64 + ty * 4];
            *(float4*)&b[0] = *(float4*)&Bs[k][tx * 4];
            *(float4*)&b[4] = *(float4*)&Bs[k][64 + tx * 4];
#pragma unroll
            for (int i = 0; i < 8; i++)
#pragma unroll
                for (int j = 0; j < 8; j++)
                    acc[i][j] += a[i] * b[j];
        }
        __syncthreads();
    }

    // Epilogue
#pragma unroll
    for (int i = 0; i < 8; i++) {
        int ml = (i < 4) ? (ty * 4 + i) : (64 + ty * 4 + i - 4);
        int m = m0 + ml;
#pragma unroll
        for (int j = 0; j < 8; j++) {
            int nl = (j < 4) ? (tx * 4 + j) : (64 + tx * 4 + j - 4);
            int n = n0 + nl;
            float v = acc[i][j] + bias[n];
            if (MODE == 0) {
                int which = n >> 11;          // 0=q, 1=k, 2=v
                int h = (n >> 7) & 15;
                int d = n & 127;
                int b = m >> 11;
                int t = m & 2047;
                size_t idx = (((size_t)b * HH + h) * TT + t) * DD + d;
                if (which == 0)       g_q[idx] = v * QKSCALE;
                else if (which == 1)  g_k[idx] = v;
                else                  g_v[idx] = v;
            } else {
                Cout[(size_t)m * N + n] = v;
            }
        }
    }
}

// ---------------------------------------------------------------------------
// Flash attention (causal), fp32. One block = 64 queries of one (b,h).
// 256 threads as 16x16: thread (ty,tx) owns S rows ty*4..+3 x cols tx*4..+3,
// and O rows ty*4..+3 x d-slice tx*8..+7. Online softmax.
// Smem (dynamic): Qs/Ks/Vs [64][132] padded, Ps [64][68] padded.
// ---------------------------------------------------------------------------
#define QPAD 132
#define PPAD 68
#define ATTN_SMEM ((3 * 64 * QPAD + 64 * PPAD) * (int)sizeof(float))

__global__ __launch_bounds__(256) void attn_kernel()
{
    extern __shared__ float sm[];
    float* Qs = sm;                     // [64][132]
    float* Ks = sm + 64 * QPAD;        // [64][132]
    float* Vs = sm + 2 * 64 * QPAD;    // [64][132]
    float* Ps = sm + 3 * 64 * QPAD;    // [64][68]

    const int tid = threadIdx.x;
    const int tx = tid & 15;
    const int ty = tid >> 4;
    const int qt = blockIdx.x;   // query tile (0..31)
    const int h  = blockIdx.y;
    const int b  = blockIdx.z;

    const size_t base = (((size_t)b * HH + h) * TT) * DD;

    // Load Q tile [64][128]
#pragma unroll
    for (int i = 0; i < 8; i++) {
        int pp = tid + i * 256;
        int row = pp >> 5;
        int d = (pp & 31) * 4;
        *(float4*)&Qs[row * QPAD + d] =
            *(const float4*)&g_q[base + (size_t)(qt * 64 + row) * DD + d];
    }

    float o[4][8];
#pragma unroll
    for (int i = 0; i < 4; i++)
#pragma unroll
        for (int d = 0; d < 8; d++) o[i][d] = 0.f;
    float mrow[4] = {-1e30f, -1e30f, -1e30f, -1e30f};
    float lrow[4] = {0.f, 0.f, 0.f, 0.f};

    for (int jt = 0; jt <= qt; jt++) {
        __syncthreads();   // previous PV / Ps reads done before overwrite
        // Load K,V tiles [64][128]
#pragma unroll
        for (int i = 0; i < 8; i++) {
            int pp = tid + i * 256;
            int row = pp >> 5;
            int d = (pp & 31) * 4;
            size_t gidx = base + (size_t)(jt * 64 + row) * DD + d;
            *(float4*)&Ks[row * QPAD + d] = *(const float4*)&g_k[gidx];
            *(float4*)&Vs[row * QPAD + d] = *(const float4*)&g_v[gidx];
        }
        __syncthreads();

        // S = Q K^T  (4x4 per thread), q already scaled by 1/sqrt(D)
        float s[4][4];
#pragma unroll
        for (int i = 0; i < 4; i++)
#pragma unroll
            for (int j = 0; j < 4; j++) s[i][j] = 0.f;

#pragma unroll 8
        for (int d0 = 0; d0 < DD; d0 += 4) {
            float4 a[4], kk[4];
#pragma unroll
            for (int i = 0; i < 4; i++)
                a[i] = *(float4*)&Qs[(ty * 4 + i) * QPAD + d0];
#pragma unroll
            for (int j = 0; j < 4; j++)
                kk[j] = *(float4*)&Ks[(tx * 4 + j) * QPAD + d0];
#pragma unroll
            for (int i = 0; i < 4; i++)
#pragma unroll
                for (int j = 0; j < 4; j++)
                    s[i][j] += a[i].x * kk[j].x + a[i].y * kk[j].y +
                               a[i].z * kk[j].z + a[i].w * kk[j].w;
        }

        // Causal mask on diagonal tile
        if (jt == qt) {
#pragma unroll
            for (int i = 0; i < 4; i++)
#pragma unroll
                for (int j = 0; j < 4; j++)
                    if (tx * 4 + j > ty * 4 + i) s[i][j] = -1e30f;
        }

        // Online softmax per row (rows ty*4+i; reduce across the 16 tx lanes)
#pragma unroll
        for (int i = 0; i < 4; i++) {
            float mx = fmaxf(fmaxf(s[i][0], s[i][1]), fmaxf(s[i][2], s[i][3]));
#pragma unroll
            for (int off = 8; off >= 1; off >>= 1)
                mx = fmaxf(mx, __shfl_xor_sync(0xffffffffu, mx, off, 16));
            float nm = fmaxf(mrow[i], mx);
            float alpha = __expf(mrow[i] - nm);
            mrow[i] = nm;
            float sum = 0.f;
#pragma unroll
            for (int j = 0; j < 4; j++) {
                float p = __expf(s[i][j] - nm);
                Ps[(ty * 4 + i) * PPAD + tx * 4 + j] = p;
                sum += p;
            }
#pragma unroll
            for (int off = 8; off >= 1; off >>= 1)
                sum += __shfl_xor_sync(0xffffffffu, sum, off, 16);
            lrow[i] = lrow[i] * alpha + sum;
#pragma unroll
            for (int d = 0; d < 8; d++) o[i][d] *= alpha;
        }
        __syncthreads();

        // O += P @ V  (thread: 4 rows x 8 d-values at tx*8)
#pragma unroll 8
        for (int col = 0; col < 64; col++) {
            float4 v0 = *(float4*)&Vs[col * QPAD + tx * 8];
            float4 v1 = *(float4*)&Vs[col * QPAD + tx * 8 + 4];
#pragma unroll
            for (int i = 0; i < 4; i++) {
                float p = Ps[(ty * 4 + i) * PPAD + col];
                o[i][0] += p * v0.x; o[i][1] += p * v0.y;
                o[i][2] += p * v0.z; o[i][3] += p * v0.w;
                o[i][4] += p * v1.x; o[i][5] += p * v1.y;
                o[i][6] += p * v1.z; o[i][7] += p * v1.w;
            }
        }
    }

    // Write normalized output to g_ao [B,T,C], c = h*128 + d
#pragma unroll
    for (int i = 0; i < 4; i++) {
        float inv = 1.f / lrow[i];
        int q = qt * 64 + ty * 4 + i;
        size_t ob = ((size_t)b * TT + q) * CC + (size_t)h * DD + tx * 8;
#pragma unroll
        for (int d = 0; d < 8; d++)
            g_ao[ob + d] = o[i][d] * inv;
    }
}

// ---------------------------------------------------------------------------
extern "C" void kernel_launch(void* const* d_in, const int* in_sizes, int n_in,
                              void* d_out, int out_size)
{
    (void)in_sizes; (void)n_in; (void)out_size;
    const float* x     = (const float*)d_in[0];
    const float* Wqkv  = (const float*)d_in[1];
    const float* bqkv  = (const float*)d_in[2];
    const float* Wproj = (const float*)d_in[3];
    const float* bproj = (const float*)d_in[4];
    float* out = (float*)d_out;

    cudaFuncSetAttribute(attn_kernel,
                         cudaFuncAttributeMaxDynamicSharedMemorySize, ATTN_SMEM);

    const int M = BB * TT;  // 8192

    // 1) QKV projection, scatter into [B,H,T,D] q/k/v (q pre-scaled)
    gemm_kernel<0><<<dim3((3 * CC) / 128, M / 128), 256>>>(
        x, Wqkv, bqkv, nullptr, M, 3 * CC, CC);

    // 2) Causal flash attention
    attn_kernel<<<dim3(TT / 64, HH, BB), 256, ATTN_SMEM>>>();

    // 3) Output projection
    gemm_kernel<1><<<dim3(CC / 128, M / 128), 256>>>(
        nullptr, Wproj, bproj, out, M, CC, CC);
}